// round 14
// baseline (speedup 1.0000x reference)
#include <cuda_runtime.h>
#include <cuda_bf16.h>

#define B_BATCH 16
#define HX 21               // hist blocks per batch (sim + labels)
#define DX 16               // dice blocks per batch (4 maps)
#define GX (HX + DX)        // 37 -> 592 CTAs = exactly 4/SM on 148 SMs
#define THREADS 256
#define NSEG 9
#define NBLOCKS (GX * B_BATCH)
#define EPSF 1e-5f
#define SIGMA_AGG 0.5f
#define SIGMA_DIS 3.0f

// Global accumulators (.bss zero-init; last block re-zeros after each call).
// g_statsF per batch: [0..8]=A (t, t!=k), [9..17]=B (t==k), [18..26]=D (k, t!=k;
// slot 18 is a dead bin), [27..32]=dice (r_inter, r_pp, r_gg, k_inter, k_pp, k_gg)
__device__ float    g_statsF[B_BATCH][33];
__device__ unsigned g_cnt[B_BATCH][18];     // [0..8]=ct, [9..17]=ck
__device__ unsigned g_count;

__global__ __launch_bounds__(THREADS, 4) void panloss_kernel(
    const float* __restrict__ pr, const float* __restrict__ rg,
    const float* __restrict__ pk, const float* __restrict__ kg,
    const float* __restrict__ sim, const int* __restrict__ tlab,
    const int* __restrict__ klab, int npix, float* __restrict__ out)
{
    __shared__ float    s_f[27 * THREADS];   // per-thread float bins, bin-major
    __shared__ unsigned s_c[9 * THREADS];    // packed: ct low16, ck high16
    __shared__ float    s_dice[6];
    __shared__ unsigned s_last;

    const int tid = threadIdx.x;
    const int b = blockIdx.y;
    const int bx = blockIdx.x;
    const int lane = tid & 31;
    const int wid = tid >> 5;
    const int nvec = npix >> 2;              // 102400, multiple of 256
    const size_t base = (size_t)b * npix;

    if (bx < HX) {
        // ── histogram role: raw-batch software pipeline (s2 deferred) ──
        for (int i = tid; i < 27 * THREADS; i += THREADS) s_f[i] = 0.f;
        __syncthreads();

        const size_t sbase = (size_t)b * 4 * npix;
        const float4* __restrict__ c0p = (const float4*)(sim + sbase);
        const float4* __restrict__ c1p = (const float4*)(sim + sbase + npix);
        const float4* __restrict__ c2p = (const float4*)(sim + sbase + 2 * (size_t)npix);
        const float4* __restrict__ c3p = (const float4*)(sim + sbase + 3 * (size_t)npix);
        const int4* __restrict__ tl4 = (const int4*)(tlab + base);
        const int4* __restrict__ kl4 = (const int4*)(klab + base);

        unsigned long long ct_acc = 0ull, ck_acc = 0ull;  // 9 x 7-bit fields
        const int stride = HX * THREADS;

        int v = bx * THREADS + tid;
        bool valid = v < nvec;               // block-uniform
        float4 c0c, c1c, c2c, c3c; int4 tlc, klc;
        if (valid) {
            c0c = __ldcs(c0p + v); c1c = __ldcs(c1p + v);
            c2c = __ldcs(c2p + v); c3c = __ldcs(c3p + v);
            tlc = __ldcs(tl4 + v); klc = __ldcs(kl4 + v);
        }
        while (valid) {
            const int vn = v + stride;
            const bool nvalid = vn < nvec;   // block-uniform
            float4 c0n, c1n, c2n, c3n; int4 tln, kln;
            if (nvalid) {                    // issue ALL next-iter loads first
                c0n = __ldcs(c0p + vn); c1n = __ldcs(c1p + vn);
                c2n = __ldcs(c2p + vn); c3n = __ldcs(c3p + vn);
                tln = __ldcs(tl4 + vn); kln = __ldcs(kl4 + vn);
            }
            // consume current batch (its loads landed an iteration ago)
#define DO_H(comp)                                                             \
            {                                                                  \
                float s2 = c0c.comp * c0c.comp + c1c.comp * c1c.comp           \
                         + c2c.comp * c2c.comp + c3c.comp * c3c.comp;          \
                int t = tlc.comp, k = klc.comp;                                \
                bool eq = (t == k);                                            \
                int bin1 = eq ? (9 + t) : t;      /* B : A */                  \
                int bin2 = eq ? 18 : (18 + k);    /* dead : D */               \
                s_f[(bin1 << 8) + tid] += s2;                                  \
                s_f[(bin2 << 8) + tid] += s2;                                  \
                ct_acc += 1ull << (t * 7);                                     \
                ck_acc += 1ull << (k * 7);                                     \
            }
            DO_H(x) DO_H(y) DO_H(z) DO_H(w)
#undef DO_H
            v = vn; valid = nvalid;
            c0c = c0n; c1c = c1n; c2c = c2n; c3c = c3n;
            tlc = tln; klc = kln;
        }

        // unpack register count fields into shared (max 80/field, fits)
#pragma unroll
        for (int bin = 0; bin < 9; bin++) {
            unsigned ctv = (unsigned)((ct_acc >> (bin * 7)) & 127u);
            unsigned ckv = (unsigned)((ck_acc >> (bin * 7)) & 127u);
            s_c[(bin << 8) + tid] = ctv | (ckv << 16);
        }
        __syncthreads();

        // 8 warps fan out over bins; lane0 -> global atomicAdd
        for (int bin = wid; bin < 27; bin += 8) {
            float vsum = 0.f;
#pragma unroll
            for (int j = 0; j < 8; j++) vsum += s_f[(bin << 8) + lane + (j << 5)];
#pragma unroll
            for (int off = 16; off; off >>= 1)
                vsum += __shfl_down_sync(0xffffffffu, vsum, off);
            if (lane == 0) atomicAdd(&g_statsF[b][bin], vsum);
        }
        for (int bin = wid; bin < 9; bin += 8) {
            unsigned csum = 0u;
#pragma unroll
            for (int j = 0; j < 8; j++) csum += s_c[(bin << 8) + lane + (j << 5)];
#pragma unroll
            for (int off = 16; off; off >>= 1)
                csum += __shfl_down_sync(0xffffffffu, csum, off);
            if (lane == 0) {
                atomicAdd(&g_cnt[b][bin], csum & 0xffffu);      // ct
                atomicAdd(&g_cnt[b][9 + bin], csum >> 16);      // ck
            }
        }
    } else {
        // ── dice role: 4 maps, software-pipelined ──
        if (tid < 6) s_dice[tid] = 0.f;
        __syncthreads();

        const float4* __restrict__ pr4 = (const float4*)(pr + base);
        const float4* __restrict__ rg4 = (const float4*)(rg + base);
        const float4* __restrict__ pk4 = (const float4*)(pk + base);
        const float4* __restrict__ kg4 = (const float4*)(kg + base);

        float d0 = 0.f, d1 = 0.f, d2 = 0.f, d3 = 0.f, d4 = 0.f, d5 = 0.f;
        const int stride = DX * THREADS;

        int v = (bx - HX) * THREADS + tid;
        bool valid = v < nvec;               // block-uniform
        float4 ac, gc, pc, kc;
        if (valid) {
            ac = __ldcs(pr4 + v); gc = __ldcs(rg4 + v);
            pc = __ldcs(pk4 + v); kc = __ldcs(kg4 + v);
        }
        while (valid) {
            const int vn = v + stride;
            const bool nvalid = vn < nvec;
            float4 an, gn, pn, kn;
            if (nvalid) {                    // prefetch next iteration
                an = __ldcs(pr4 + vn); gn = __ldcs(rg4 + vn);
                pn = __ldcs(pk4 + vn); kn = __ldcs(kg4 + vn);
            }
#define DO_D(comp)                                                             \
            {                                                                  \
                float sg = 1.f / (1.f + __expf(-ac.comp));                     \
                float gv = gc.comp;                                            \
                d0 += sg * gv; d1 += sg * sg; d2 += gv * gv;                   \
                sg = 1.f / (1.f + __expf(-pc.comp));                           \
                gv = kc.comp;                                                  \
                d3 += sg * gv; d4 += sg * sg; d5 += gv * gv;                   \
            }
            DO_D(x) DO_D(y) DO_D(z) DO_D(w)
#undef DO_D
            v = vn; valid = nvalid;
            ac = an; gc = gn; pc = pn; kc = kn;
        }

#pragma unroll
        for (int off = 16; off; off >>= 1) {
            d0 += __shfl_down_sync(0xffffffffu, d0, off);
            d1 += __shfl_down_sync(0xffffffffu, d1, off);
            d2 += __shfl_down_sync(0xffffffffu, d2, off);
            d3 += __shfl_down_sync(0xffffffffu, d3, off);
            d4 += __shfl_down_sync(0xffffffffu, d4, off);
            d5 += __shfl_down_sync(0xffffffffu, d5, off);
        }
        if (lane == 0) {
            atomicAdd(&s_dice[0], d0);
            atomicAdd(&s_dice[1], d1);
            atomicAdd(&s_dice[2], d2);
            atomicAdd(&s_dice[3], d3);
            atomicAdd(&s_dice[4], d4);
            atomicAdd(&s_dice[5], d5);
        }
        __syncthreads();
        if (tid < 6) atomicAdd(&g_statsF[b][27 + tid], s_dice[tid]);
    }

    // Last-block-done: fence, bump counter, last block finalizes.
    __threadfence();
    if (tid == 0)
        s_last = (atomicAdd(&g_count, 1u) == (unsigned)(NBLOCKS - 1));
    __syncthreads();
    if (!s_last) return;
    __threadfence();

    if (tid < 32) {
        float lr = 0.f, lk = 0.f, lagg = 0.f, ldis = 0.f;
        if (tid < B_BATCH) {
            const float* s = g_statsF[tid];
            const unsigned* c = g_cnt[tid];
            float inter = s[27], pp = s[28], gg = s[29];
            lr = 1.f - (2.f * inter + EPSF) / ((pp + EPSF) + (gg + EPSF));
            inter = s[30]; pp = s[31]; gg = s[32];
            lk = 1.f - (2.f * inter + EPSF) / ((pp + EPSF) + (gg + EPSF));

            float av[NSEG - 1];
#pragma unroll
            for (int i = 1; i < NSEG; i++) {
                float ct = (float)c[i];
                float ck = (float)c[9 + i];
                float A = s[i], Bv = s[9 + i], D = s[18 + i];
                float inv = 1.f / (ck + 1.f);
                float omi = 1.f - inv;
                float n2 = A + Bv * omi * omi + D * inv * inv;
                float tt = sqrtf(n2) - SIGMA_AGG;       // no clamp (matches ref)
                lagg += logf(tt * tt + 1.f) / (ct + 1.f);
                float den = ck + 0.001f;
                av[i - 1] = (Bv + D) / (den * den);
            }
#pragma unroll
            for (int i = 0; i < NSEG - 1; i++)
#pragma unroll
                for (int j = i + 1; j < NSEG - 1; j++) {
                    float p = SIGMA_DIS - sqrtf(av[i] + av[j]);
                    ldis += logf(p * p + 1.f);
                }
            ldis *= (1.f / 56.f);                       // K_MAX*(K_MAX-1)
        }
#pragma unroll
        for (int off = 16; off; off >>= 1) {
            lr   += __shfl_down_sync(0xffffffffu, lr,   off);
            lk   += __shfl_down_sync(0xffffffffu, lk,   off);
            lagg += __shfl_down_sync(0xffffffffu, lagg, off);
            ldis += __shfl_down_sync(0xffffffffu, ldis, off);
        }
        if (tid == 0) {
            out[0] = lr + 0.5f * lk + 0.25f * (lagg + ldis);
            out[1] = lr;
            out[2] = lk;
            out[3] = lagg;
            out[4] = ldis;
        }
    }
    __syncthreads();
    // Re-zero accumulators for the next graph replay.
    for (int i = tid; i < B_BATCH * 33; i += THREADS) ((float*)g_statsF)[i] = 0.f;
    for (int i = tid; i < B_BATCH * 18; i += THREADS) ((unsigned*)g_cnt)[i] = 0u;
    if (tid == 0) g_count = 0u;
}

extern "C" void kernel_launch(void* const* d_in, const int* in_sizes, int n_in,
                              void* d_out, int out_size)
{
    const float* pr  = (const float*)d_in[0];   // pred_regions
    const float* rg  = (const float*)d_in[1];   // regions_gt
    const float* pk  = (const float*)d_in[2];   // pred_kernels
    const float* kg  = (const float*)d_in[3];   // kernels_gt
    const float* sim = (const float*)d_in[4];   // pred_similarities (B,4,H,W)
    const int*   tl  = (const int*)d_in[5];     // text labels
    const int*   kl  = (const int*)d_in[6];     // kernel labels
    const int npix = in_sizes[0] / B_BATCH;     // H*W = 409600

    dim3 grid(GX, B_BATCH);                     // 592 CTAs = 4/SM, single wave
    panloss_kernel<<<grid, THREADS>>>(pr, rg, pk, kg, sim, tl, kl, npix,
                                      (float*)d_out);
}

// round 16
// speedup vs baseline: 1.1822x; 1.1822x over previous
#include <cuda_runtime.h>
#include <cuda_bf16.h>

#define B_BATCH 16
#define HX 22               // hist blocks per batch (sim + labels)
#define DX 15               // dice blocks per batch (4 maps)
#define GX (HX + DX)        // 37 -> 592 CTAs = exactly 4/SM on 148 SMs
#define THREADS 256
#define NSEG 9
#define NBLOCKS (GX * B_BATCH)
#define EPSF 1e-5f
#define SIGMA_AGG 0.5f
#define SIGMA_DIS 3.0f

__device__ __forceinline__ void prefetch_l2(const void* p) {
    asm volatile("prefetch.global.L2 [%0];" :: "l"(p));
}

// Global accumulators (.bss zero-init; last block re-zeros after each call).
// g_statsF per batch: [0..8]=A (t, t!=k), [9..17]=B (t==k), [18..26]=D (k, t!=k;
// slot 18 is a dead bin), [27..32]=dice (r_inter, r_pp, r_gg, k_inter, k_pp, k_gg)
__device__ float    g_statsF[B_BATCH][33];
__device__ unsigned g_cnt[B_BATCH][18];     // [0..8]=ct, [9..17]=ck
__device__ unsigned g_count;

__global__ __launch_bounds__(THREADS, 4) void panloss_kernel(
    const float* __restrict__ pr, const float* __restrict__ rg,
    const float* __restrict__ pk, const float* __restrict__ kg,
    const float* __restrict__ sim, const int* __restrict__ tlab,
    const int* __restrict__ klab, int npix, float* __restrict__ out)
{
    __shared__ float    s_f[27 * THREADS];   // per-thread float bins, bin-major
    __shared__ unsigned s_c[9 * THREADS];    // packed: ct low16, ck high16
    __shared__ float    s_dice[6];
    __shared__ unsigned s_last;

    const int tid = threadIdx.x;
    const int b = blockIdx.y;
    const int bx = blockIdx.x;
    const int lane = tid & 31;
    const int wid = tid >> 5;
    const int nvec = npix >> 2;              // 102400, multiple of 256
    const size_t base = (size_t)b * npix;
    const bool pf_lane = (tid & 7) == 0;     // one prefetch per 128B line

    if (bx < HX) {
        // ── histogram role: sim (4ch) + labels, reg-prefetch + L2-prefetch ──
        for (int i = tid; i < 27 * THREADS; i += THREADS) s_f[i] = 0.f;
        __syncthreads();

        const size_t sbase = (size_t)b * 4 * npix;
        const float4* __restrict__ c0p = (const float4*)(sim + sbase);
        const float4* __restrict__ c1p = (const float4*)(sim + sbase + npix);
        const float4* __restrict__ c2p = (const float4*)(sim + sbase + 2 * (size_t)npix);
        const float4* __restrict__ c3p = (const float4*)(sim + sbase + 3 * (size_t)npix);
        const int4* __restrict__ tl4 = (const int4*)(tlab + base);
        const int4* __restrict__ kl4 = (const int4*)(klab + base);

        unsigned long long ct_acc = 0ull, ck_acc = 0ull;  // 9 x 7-bit fields
        const int stride = HX * THREADS;

        int v = bx * THREADS + tid;
        bool valid = v < nvec;               // block-uniform
        float4 s2c; int4 tlc, klc;
        if (valid) {
            // L2-prefetch the first two future iterations
            if (pf_lane) {
                int vp = v + stride;
                if (vp < nvec) {
                    prefetch_l2(c0p + vp); prefetch_l2(c1p + vp);
                    prefetch_l2(c2p + vp); prefetch_l2(c3p + vp);
                    prefetch_l2(tl4 + vp); prefetch_l2(kl4 + vp);
                }
            }
            float4 c0 = __ldcs(c0p + v), c1 = __ldcs(c1p + v);
            float4 c2 = __ldcs(c2p + v), c3 = __ldcs(c3p + v);
            tlc = __ldcs(tl4 + v);  klc = __ldcs(kl4 + v);
            s2c.x = c0.x*c0.x + c1.x*c1.x + c2.x*c2.x + c3.x*c3.x;
            s2c.y = c0.y*c0.y + c1.y*c1.y + c2.y*c2.y + c3.y*c3.y;
            s2c.z = c0.z*c0.z + c1.z*c1.z + c2.z*c2.z + c3.z*c3.z;
            s2c.w = c0.w*c0.w + c1.w*c1.w + c2.w*c2.w + c3.w*c3.w;
        }
        while (valid) {
            const int vn = v + stride;
            const bool nvalid = vn < nvec;   // block-uniform
            float4 c0n, c1n, c2n, c3n; int4 tln, kln;
            if (nvalid) {                    // issue next-iter demand loads (L2 hits)
                c0n = __ldcs(c0p + vn); c1n = __ldcs(c1p + vn);
                c2n = __ldcs(c2p + vn); c3n = __ldcs(c3p + vn);
                tln = __ldcs(tl4 + vn); kln = __ldcs(kl4 + vn);
                const int v2 = vn + stride;  // L2-prefetch two ahead
                if (v2 < nvec && pf_lane) {
                    prefetch_l2(c0p + v2); prefetch_l2(c1p + v2);
                    prefetch_l2(c2p + v2); prefetch_l2(c3p + v2);
                    prefetch_l2(tl4 + v2); prefetch_l2(kl4 + v2);
                }
            }
            // consume current batch (loads landed an iteration ago)
#define DO_H(comp)                                                             \
            {                                                                  \
                float s2 = s2c.comp;                                           \
                int t = tlc.comp, k = klc.comp;                                \
                bool eq = (t == k);                                            \
                int bin1 = eq ? (9 + t) : t;      /* B : A */                  \
                int bin2 = eq ? 18 : (18 + k);    /* dead : D */               \
                s_f[(bin1 << 8) + tid] += s2;                                  \
                s_f[(bin2 << 8) + tid] += s2;                                  \
                ct_acc += 1ull << (t * 7);                                     \
                ck_acc += 1ull << (k * 7);                                     \
            }
            DO_H(x) DO_H(y) DO_H(z) DO_H(w)
#undef DO_H
            // reduce the next batch to s2 AFTER consuming (gives loads time to land)
            if (nvalid) {
                s2c.x = c0n.x*c0n.x + c1n.x*c1n.x + c2n.x*c2n.x + c3n.x*c3n.x;
                s2c.y = c0n.y*c0n.y + c1n.y*c1n.y + c2n.y*c2n.y + c3n.y*c3n.y;
                s2c.z = c0n.z*c0n.z + c1n.z*c1n.z + c2n.z*c2n.z + c3n.z*c3n.z;
                s2c.w = c0n.w*c0n.w + c1n.w*c1n.w + c2n.w*c2n.w + c3n.w*c3n.w;
                tlc = tln; klc = kln;
            }
            v = vn; valid = nvalid;
        }

        // unpack register count fields into shared (max 76/field, fits 16 bits)
#pragma unroll
        for (int bin = 0; bin < 9; bin++) {
            unsigned ctv = (unsigned)((ct_acc >> (bin * 7)) & 127u);
            unsigned ckv = (unsigned)((ck_acc >> (bin * 7)) & 127u);
            s_c[(bin << 8) + tid] = ctv | (ckv << 16);
        }
        __syncthreads();

        // 8 warps fan out over bins; lane0 -> global atomicAdd
        for (int bin = wid; bin < 27; bin += 8) {
            float vsum = 0.f;
#pragma unroll
            for (int j = 0; j < 8; j++) vsum += s_f[(bin << 8) + lane + (j << 5)];
#pragma unroll
            for (int off = 16; off; off >>= 1)
                vsum += __shfl_down_sync(0xffffffffu, vsum, off);
            if (lane == 0) atomicAdd(&g_statsF[b][bin], vsum);
        }
        for (int bin = wid; bin < 9; bin += 8) {
            unsigned csum = 0u;
#pragma unroll
            for (int j = 0; j < 8; j++) csum += s_c[(bin << 8) + lane + (j << 5)];
#pragma unroll
            for (int off = 16; off; off >>= 1)
                csum += __shfl_down_sync(0xffffffffu, csum, off);
            if (lane == 0) {
                atomicAdd(&g_cnt[b][bin], csum & 0xffffu);      // ct
                atomicAdd(&g_cnt[b][9 + bin], csum >> 16);      // ck
            }
        }
    } else {
        // ── dice role: 4 maps, reg-prefetch + L2-prefetch ──
        if (tid < 6) s_dice[tid] = 0.f;
        __syncthreads();

        const float4* __restrict__ pr4 = (const float4*)(pr + base);
        const float4* __restrict__ rg4 = (const float4*)(rg + base);
        const float4* __restrict__ pk4 = (const float4*)(pk + base);
        const float4* __restrict__ kg4 = (const float4*)(kg + base);

        float d0 = 0.f, d1 = 0.f, d2 = 0.f, d3 = 0.f, d4 = 0.f, d5 = 0.f;
        const int stride = DX * THREADS;

        int v = (bx - HX) * THREADS + tid;
        bool valid = v < nvec;               // block-uniform
        float4 ac, gc, pc, kc;
        if (valid) {
            if (pf_lane) {
                int vp = v + stride;
                if (vp < nvec) {
                    prefetch_l2(pr4 + vp); prefetch_l2(rg4 + vp);
                    prefetch_l2(pk4 + vp); prefetch_l2(kg4 + vp);
                }
            }
            ac = __ldcs(pr4 + v); gc = __ldcs(rg4 + v);
            pc = __ldcs(pk4 + v); kc = __ldcs(kg4 + v);
        }
        while (valid) {
            const int vn = v + stride;
            const bool nvalid = vn < nvec;
            float4 an, gn, pn, kn;
            if (nvalid) {                    // demand-load next iteration (L2 hits)
                an = __ldcs(pr4 + vn); gn = __ldcs(rg4 + vn);
                pn = __ldcs(pk4 + vn); kn = __ldcs(kg4 + vn);
                const int v2 = vn + stride;
                if (v2 < nvec && pf_lane) {
                    prefetch_l2(pr4 + v2); prefetch_l2(rg4 + v2);
                    prefetch_l2(pk4 + v2); prefetch_l2(kg4 + v2);
                }
            }
#define DO_D(comp)                                                             \
            {                                                                  \
                float sg = 1.f / (1.f + __expf(-ac.comp));                     \
                float gv = gc.comp;                                            \
                d0 += sg * gv; d1 += sg * sg; d2 += gv * gv;                   \
                sg = 1.f / (1.f + __expf(-pc.comp));                           \
                gv = kc.comp;                                                  \
                d3 += sg * gv; d4 += sg * sg; d5 += gv * gv;                   \
            }
            DO_D(x) DO_D(y) DO_D(z) DO_D(w)
#undef DO_D
            v = vn; valid = nvalid;
            ac = an; gc = gn; pc = pn; kc = kn;
        }

#pragma unroll
        for (int off = 16; off; off >>= 1) {
            d0 += __shfl_down_sync(0xffffffffu, d0, off);
            d1 += __shfl_down_sync(0xffffffffu, d1, off);
            d2 += __shfl_down_sync(0xffffffffu, d2, off);
            d3 += __shfl_down_sync(0xffffffffu, d3, off);
            d4 += __shfl_down_sync(0xffffffffu, d4, off);
            d5 += __shfl_down_sync(0xffffffffu, d5, off);
        }
        if (lane == 0) {
            atomicAdd(&s_dice[0], d0);
            atomicAdd(&s_dice[1], d1);
            atomicAdd(&s_dice[2], d2);
            atomicAdd(&s_dice[3], d3);
            atomicAdd(&s_dice[4], d4);
            atomicAdd(&s_dice[5], d5);
        }
        __syncthreads();
        if (tid < 6) atomicAdd(&g_statsF[b][27 + tid], s_dice[tid]);
    }

    // Last-block-done: fence, bump counter, last block finalizes.
    __threadfence();
    if (tid == 0)
        s_last = (atomicAdd(&g_count, 1u) == (unsigned)(NBLOCKS - 1));
    __syncthreads();
    if (!s_last) return;
    __threadfence();

    if (tid < 32) {
        float lr = 0.f, lk = 0.f, lagg = 0.f, ldis = 0.f;
        if (tid < B_BATCH) {
            const float* s = g_statsF[tid];
            const unsigned* c = g_cnt[tid];
            float inter = s[27], pp = s[28], gg = s[29];
            lr = 1.f - (2.f * inter + EPSF) / ((pp + EPSF) + (gg + EPSF));
            inter = s[30]; pp = s[31]; gg = s[32];
            lk = 1.f - (2.f * inter + EPSF) / ((pp + EPSF) + (gg + EPSF));

            float av[NSEG - 1];
#pragma unroll
            for (int i = 1; i < NSEG; i++) {
                float ct = (float)c[i];
                float ck = (float)c[9 + i];
                float A = s[i], Bv = s[9 + i], D = s[18 + i];
                float inv = 1.f / (ck + 1.f);
                float omi = 1.f - inv;
                float n2 = A + Bv * omi * omi + D * inv * inv;
                float tt = sqrtf(n2) - SIGMA_AGG;       // no clamp (matches ref)
                lagg += logf(tt * tt + 1.f) / (ct + 1.f);
                float den = ck + 0.001f;
                av[i - 1] = (Bv + D) / (den * den);
            }
#pragma unroll
            for (int i = 0; i < NSEG - 1; i++)
#pragma unroll
                for (int j = i + 1; j < NSEG - 1; j++) {
                    float p = SIGMA_DIS - sqrtf(av[i] + av[j]);
                    ldis += logf(p * p + 1.f);
                }
            ldis *= (1.f / 56.f);                       // K_MAX*(K_MAX-1)
        }
#pragma unroll
        for (int off = 16; off; off >>= 1) {
            lr   += __shfl_down_sync(0xffffffffu, lr,   off);
            lk   += __shfl_down_sync(0xffffffffu, lk,   off);
            lagg += __shfl_down_sync(0xffffffffu, lagg, off);
            ldis += __shfl_down_sync(0xffffffffu, ldis, off);
        }
        if (tid == 0) {
            out[0] = lr + 0.5f * lk + 0.25f * (lagg + ldis);
            out[1] = lr;
            out[2] = lk;
            out[3] = lagg;
            out[4] = ldis;
        }
    }
    __syncthreads();
    // Re-zero accumulators for the next graph replay.
    for (int i = tid; i < B_BATCH * 33; i += THREADS) ((float*)g_statsF)[i] = 0.f;
    for (int i = tid; i < B_BATCH * 18; i += THREADS) ((unsigned*)g_cnt)[i] = 0u;
    if (tid == 0) g_count = 0u;
}

extern "C" void kernel_launch(void* const* d_in, const int* in_sizes, int n_in,
                              void* d_out, int out_size)
{
    const float* pr  = (const float*)d_in[0];   // pred_regions
    const float* rg  = (const float*)d_in[1];   // regions_gt
    const float* pk  = (const float*)d_in[2];   // pred_kernels
    const float* kg  = (const float*)d_in[3];   // kernels_gt
    const float* sim = (const float*)d_in[4];   // pred_similarities (B,4,H,W)
    const int*   tl  = (const int*)d_in[5];     // text labels
    const int*   kl  = (const int*)d_in[6];     // kernel labels
    const int npix = in_sizes[0] / B_BATCH;     // H*W = 409600

    dim3 grid(GX, B_BATCH);                     // 592 CTAs = 4/SM, single wave
    panloss_kernel<<<grid, THREADS>>>(pr, rg, pk, kg, sim, tl, kl, npix,
                                      (float*)d_out);
}